// round 3
// baseline (speedup 1.0000x reference)
#include <cuda_runtime.h>
#include <cstdint>

// RelationalKENN on GB300.
// Phase A: u = unary + unary_enhance(unary)         (100K x 16)
// Phase B: per-edge 3-literal softmax clauses, bp = binary + db,
//          up = u scatter-added with du1/du2 via red.global.add.v4.f32.
// Edge kernel is L1tex-wavefront bound (4 random sector ops/edge); this
// version batches 4 edges/thread to maximize LSU MLP.

#define MAX_NODES 100000
#define EPT 4   // edges per thread

__device__ float g_u03[MAX_NODES * 4];   // clean copy of u[:,0:4]

static __device__ __forceinline__ void clause2(float xa, float xb,
                                               float sa, float sb, float w,
                                               float &da, float &db) {
    float s0 = xa * sa, s1 = xb * sb;
    float m  = fmaxf(s0, s1);
    float e0 = __expf(s0 - m), e1 = __expf(s1 - m);
    float inv = __fdividef(w, e0 + e1);
    da += sa * e0 * inv;
    db += sb * e1 * inv;
}

static __device__ __forceinline__ void clause3(float xa, float xb, float xc,
                                               float sa, float sb, float sc, float w,
                                               float &da, float &db, float &dc) {
    float s0 = xa * sa, s1 = xb * sb, s2 = xc * sc;
    float m  = fmaxf(fmaxf(s0, s1), s2);
    float e0 = __expf(s0 - m), e1 = __expf(s1 - m), e2 = __expf(s2 - m);
    float inv = __fdividef(w, e0 + e1 + e2);
    da += sa * e0 * inv;
    db += sb * e1 * inv;
    dc += sc * e2 * inv;
}

__global__ void __launch_bounds__(256)
unary_kernel(const float* __restrict__ unary,
             const float* __restrict__ uw,
             float* __restrict__ up,
             int n_nodes) {
    int i = blockIdx.x * blockDim.x + threadIdx.x;
    if (i >= n_nodes) return;

    const float4* in4 = reinterpret_cast<const float4*>(unary + (size_t)i * 16);
    float x[16];
    {
        float4 t0 = in4[0], t1 = in4[1], t2 = in4[2], t3 = in4[3];
        x[0]=t0.x; x[1]=t0.y; x[2]=t0.z;  x[3]=t0.w;
        x[4]=t1.x; x[5]=t1.y; x[6]=t1.z;  x[7]=t1.w;
        x[8]=t2.x; x[9]=t2.y; x[10]=t2.z; x[11]=t2.w;
        x[12]=t3.x; x[13]=t3.y; x[14]=t3.z; x[15]=t3.w;
    }

    float w0=__ldg(uw+0), w1=__ldg(uw+1), w2=__ldg(uw+2), w3=__ldg(uw+3);
    float w4=__ldg(uw+4), w5=__ldg(uw+5), w6=__ldg(uw+6), w7=__ldg(uw+7);

    float d[16];
#pragma unroll
    for (int k = 0; k < 16; k++) d[k] = 0.0f;

    clause2(x[0],  x[1],          -1.f, 1.f,       w0, d[0],  d[1]);
    clause2(x[1],  x[2],          -1.f, 1.f,       w1, d[1],  d[2]);
    clause3(x[2],  x[3],  x[4],   -1.f, 1.f, 1.f,  w2, d[2],  d[3],  d[4]);
    clause2(x[4],  x[5],          -1.f, 1.f,       w3, d[4],  d[5]);
    clause3(x[6],  x[7],  x[8],   -1.f, 1.f, 1.f,  w4, d[6],  d[7],  d[8]);
    clause2(x[8],  x[9],          -1.f, 1.f,       w5, d[8],  d[9]);
    clause3(x[10], x[11], x[12],  -1.f, 1.f, 1.f,  w6, d[10], d[11], d[12]);
    clause3(x[13], x[14], x[15],  -1.f, 1.f, 1.f,  w7, d[13], d[14], d[15]);

    float u[16];
#pragma unroll
    for (int k = 0; k < 16; k++) u[k] = x[k] + d[k];

    float4* out4 = reinterpret_cast<float4*>(up + (size_t)i * 16);
    out4[0] = make_float4(u[0],  u[1],  u[2],  u[3]);
    out4[1] = make_float4(u[4],  u[5],  u[6],  u[7]);
    out4[2] = make_float4(u[8],  u[9],  u[10], u[11]);
    out4[3] = make_float4(u[12], u[13], u[14], u[15]);

    reinterpret_cast<float4*>(g_u03)[i] = make_float4(u[0], u[1], u[2], u[3]);
}

static __device__ __forceinline__ void red_add_v4(float* addr,
                                                  float a, float b, float c, float d) {
    asm volatile("red.global.add.v4.f32 [%0], {%1,%2,%3,%4};"
                 :: "l"(addr), "f"(a), "f"(b), "f"(c), "f"(d)
                 : "memory");
}

// Per-edge math: clause i on joined vector is sel = [-u1_i, -b_i, +u2_i].
static __device__ __forceinline__ void edge_math(const float4& a, const float4& c,
                                                 const float4& b,
                                                 float w0, float w1, float w2, float w3,
                                                 float4& du1, float4& du2, float4& bpv) {
    float av[4] = {a.x, a.y, a.z, a.w};
    float cv[4] = {c.x, c.y, c.z, c.w};
    float bv[4] = {b.x, b.y, b.z, b.w};
    float wv[4] = {w0, w1, w2, w3};
    float d1[4], d2[4], bo[4];
#pragma unroll
    for (int i = 0; i < 4; i++) {
        float s0 = -av[i];
        float s1 = -bv[i];
        float s2 =  cv[i];
        float m  = fmaxf(fmaxf(s0, s1), s2);
        float e0 = __expf(s0 - m);
        float e1 = __expf(s1 - m);
        float e2 = __expf(s2 - m);
        float inv = __fdividef(wv[i], e0 + e1 + e2);
        d1[i] = -e0 * inv;
        bo[i] = bv[i] - e1 * inv;
        d2[i] =  e2 * inv;
    }
    du1 = make_float4(d1[0], d1[1], d1[2], d1[3]);
    du2 = make_float4(d2[0], d2[1], d2[2], d2[3]);
    bpv = make_float4(bo[0], bo[1], bo[2], bo[3]);
}

__global__ void __launch_bounds__(256, 3)
edge_kernel(const float* __restrict__ binary,
            const int*   __restrict__ index1,
            const int*   __restrict__ index2,
            const float* __restrict__ bw,
            float* __restrict__ up,
            float* __restrict__ bp,
            int n_edges) {
    int base = (blockIdx.x * blockDim.x + threadIdx.x) * EPT;
    if (base >= n_edges) return;

    float w0=__ldg(bw+0), w1=__ldg(bw+1), w2=__ldg(bw+2), w3=__ldg(bw+3);

    const float4* u03 = reinterpret_cast<const float4*>(g_u03);

    if (base + EPT <= n_edges) {
        // ---- fast path: fully batched, maximal MLP ----
        int4 idx1 = *reinterpret_cast<const int4*>(index1 + base);
        int4 idx2 = *reinterpret_cast<const int4*>(index2 + base);
        int i1[EPT] = {idx1.x, idx1.y, idx1.z, idx1.w};
        int i2[EPT] = {idx2.x, idx2.y, idx2.z, idx2.w};

        // Issue all 8 gathers back-to-back (independent -> MLP=8).
        float4 g1[EPT], g2[EPT];
#pragma unroll
        for (int k = 0; k < EPT; k++) g1[k] = __ldg(u03 + i1[k]);
#pragma unroll
        for (int k = 0; k < EPT; k++) g2[k] = __ldg(u03 + i2[k]);

        // Binary loads.
        float4 bv[EPT];
#pragma unroll
        for (int k = 0; k < EPT; k++)
            bv[k] = reinterpret_cast<const float4*>(binary)[base + k];

        float4 du1[EPT], du2[EPT], bpv[EPT];
#pragma unroll
        for (int k = 0; k < EPT; k++)
            edge_math(g1[k], g2[k], bv[k], w0, w1, w2, w3,
                      du1[k], du2[k], bpv[k]);

        // Stores first (fire-and-forget), then the 8 REDs.
#pragma unroll
        for (int k = 0; k < EPT; k++)
            reinterpret_cast<float4*>(bp)[base + k] = bpv[k];
#pragma unroll
        for (int k = 0; k < EPT; k++) {
            red_add_v4(up + (size_t)i1[k] * 16, du1[k].x, du1[k].y, du1[k].z, du1[k].w);
            red_add_v4(up + (size_t)i2[k] * 16, du2[k].x, du2[k].y, du2[k].z, du2[k].w);
        }
    } else {
        // ---- tail path ----
        for (int e = base; e < n_edges; e++) {
            int i1 = index1[e];
            int i2 = index2[e];
            float4 a = __ldg(u03 + i1);
            float4 c = __ldg(u03 + i2);
            float4 b = reinterpret_cast<const float4*>(binary)[e];
            float4 du1, du2, bpv;
            edge_math(a, c, b, w0, w1, w2, w3, du1, du2, bpv);
            reinterpret_cast<float4*>(bp)[e] = bpv;
            red_add_v4(up + (size_t)i1 * 16, du1.x, du1.y, du1.z, du1.w);
            red_add_v4(up + (size_t)i2 * 16, du2.x, du2.y, du2.z, du2.w);
        }
    }
}

extern "C" void kernel_launch(void* const* d_in, const int* in_sizes, int n_in,
                              void* d_out, int out_size) {
    const float* unary   = (const float*)d_in[0];
    const float* binary  = (const float*)d_in[1];
    const int*   index1  = (const int*)  d_in[2];
    const int*   index2  = (const int*)  d_in[3];
    const float* uw      = (const float*)d_in[4];
    const float* bw      = (const float*)d_in[5];

    int n_nodes = in_sizes[0] / 16;
    int n_edges = in_sizes[1] / 4;

    float* up = (float*)d_out;
    float* bp = up + (size_t)n_nodes * 16;

    unary_kernel<<<(n_nodes + 255) / 256, 256>>>(unary, uw, up, n_nodes);

    int threads_needed = (n_edges + EPT - 1) / EPT;
    edge_kernel<<<(threads_needed + 255) / 256, 256>>>(binary, index1, index2, bw,
                                                       up, bp, n_edges);
}

// round 5
// speedup vs baseline: 1.0992x; 1.0992x over previous
#include <cuda_runtime.h>
#include <cstdint>

// RelationalKENN on GB300.
// Phase A: u = unary + unary_enhance(unary)         (100K x 16)
// Phase B: per-edge 3-literal softmax clauses, bp = binary + db,
//          up scatter-added via red.global.add.v4.f32.
// Edge kernel is L1tex-wavefront + LTS co-limited (4 random 16B ops/edge).
// R3: persistent one-wave grid-stride edge kernel, EPT=1 register footprint.

#define MAX_NODES 100000

__device__ float g_u03[MAX_NODES * 4];   // clean copy of u[:,0:4]

static __device__ __forceinline__ void clause2(float xa, float xb,
                                               float sa, float sb, float w,
                                               float &da, float &db) {
    float s0 = xa * sa, s1 = xb * sb;
    float m  = fmaxf(s0, s1);
    float e0 = __expf(s0 - m), e1 = __expf(s1 - m);
    float inv = __fdividef(w, e0 + e1);
    da += sa * e0 * inv;
    db += sb * e1 * inv;
}

static __device__ __forceinline__ void clause3(float xa, float xb, float xc,
                                               float sa, float sb, float sc, float w,
                                               float &da, float &db, float &dc) {
    float s0 = xa * sa, s1 = xb * sb, s2 = xc * sc;
    float m  = fmaxf(fmaxf(s0, s1), s2);
    float e0 = __expf(s0 - m), e1 = __expf(s1 - m), e2 = __expf(s2 - m);
    float inv = __fdividef(w, e0 + e1 + e2);
    da += sa * e0 * inv;
    db += sb * e1 * inv;
    dc += sc * e2 * inv;
}

__global__ void __launch_bounds__(256)
unary_kernel(const float* __restrict__ unary,
             const float* __restrict__ uw,
             float* __restrict__ up,
             int n_nodes) {
    int i = blockIdx.x * blockDim.x + threadIdx.x;
    if (i >= n_nodes) return;

    const float4* in4 = reinterpret_cast<const float4*>(unary + (size_t)i * 16);
    float x[16];
    {
        float4 t0 = in4[0], t1 = in4[1], t2 = in4[2], t3 = in4[3];
        x[0]=t0.x; x[1]=t0.y; x[2]=t0.z;  x[3]=t0.w;
        x[4]=t1.x; x[5]=t1.y; x[6]=t1.z;  x[7]=t1.w;
        x[8]=t2.x; x[9]=t2.y; x[10]=t2.z; x[11]=t2.w;
        x[12]=t3.x; x[13]=t3.y; x[14]=t3.z; x[15]=t3.w;
    }

    float w0=__ldg(uw+0), w1=__ldg(uw+1), w2=__ldg(uw+2), w3=__ldg(uw+3);
    float w4=__ldg(uw+4), w5=__ldg(uw+5), w6=__ldg(uw+6), w7=__ldg(uw+7);

    float d[16];
#pragma unroll
    for (int k = 0; k < 16; k++) d[k] = 0.0f;

    clause2(x[0],  x[1],          -1.f, 1.f,       w0, d[0],  d[1]);
    clause2(x[1],  x[2],          -1.f, 1.f,       w1, d[1],  d[2]);
    clause3(x[2],  x[3],  x[4],   -1.f, 1.f, 1.f,  w2, d[2],  d[3],  d[4]);
    clause2(x[4],  x[5],          -1.f, 1.f,       w3, d[4],  d[5]);
    clause3(x[6],  x[7],  x[8],   -1.f, 1.f, 1.f,  w4, d[6],  d[7],  d[8]);
    clause2(x[8],  x[9],          -1.f, 1.f,       w5, d[8],  d[9]);
    clause3(x[10], x[11], x[12],  -1.f, 1.f, 1.f,  w6, d[10], d[11], d[12]);
    clause3(x[13], x[14], x[15],  -1.f, 1.f, 1.f,  w7, d[13], d[14], d[15]);

    float u[16];
#pragma unroll
    for (int k = 0; k < 16; k++) u[k] = x[k] + d[k];

    float4* out4 = reinterpret_cast<float4*>(up + (size_t)i * 16);
    out4[0] = make_float4(u[0],  u[1],  u[2],  u[3]);
    out4[1] = make_float4(u[4],  u[5],  u[6],  u[7]);
    out4[2] = make_float4(u[8],  u[9],  u[10], u[11]);
    out4[3] = make_float4(u[12], u[13], u[14], u[15]);

    reinterpret_cast<float4*>(g_u03)[i] = make_float4(u[0], u[1], u[2], u[3]);
}

static __device__ __forceinline__ void red_add_v4(float* addr,
                                                  float a, float b, float c, float d) {
    asm volatile("red.global.add.v4.f32 [%0], {%1,%2,%3,%4};"
                 :: "l"(addr), "f"(a), "f"(b), "f"(c), "f"(d)
                 : "memory");
}

static __device__ __forceinline__ float4 ldcs_f4(const float4* p) {
    float4 v;
    asm volatile("ld.global.cs.v4.f32 {%0,%1,%2,%3}, [%4];"
                 : "=f"(v.x), "=f"(v.y), "=f"(v.z), "=f"(v.w) : "l"(p));
    return v;
}

static __device__ __forceinline__ void stcs_f4(float4* p, float4 v) {
    asm volatile("st.global.cs.v4.f32 [%0], {%1,%2,%3,%4};"
                 :: "l"(p), "f"(v.x), "f"(v.y), "f"(v.z), "f"(v.w) : "memory");
}

__global__ void __launch_bounds__(256)
edge_kernel(const float* __restrict__ binary,
            const int*   __restrict__ index1,
            const int*   __restrict__ index2,
            const float* __restrict__ bw,
            float* __restrict__ up,
            float* __restrict__ bp,
            int n_edges) {
    const float w0=__ldg(bw+0), w1=__ldg(bw+1), w2=__ldg(bw+2), w3=__ldg(bw+3);
    const float4* u03 = reinterpret_cast<const float4*>(g_u03);
    const int stride = gridDim.x * blockDim.x;

    for (int e = blockIdx.x * blockDim.x + threadIdx.x; e < n_edges; e += stride) {
        int i1 = index1[e];
        int i2 = index2[e];

        float4 a = __ldg(u03 + i1);    // u[index1][0:4]   (L2-resident table)
        float4 c = __ldg(u03 + i2);    // u[index2][0:4]
        float4 b = ldcs_f4(reinterpret_cast<const float4*>(binary) + e);  // streaming

        float av[4] = {a.x, a.y, a.z, a.w};
        float cv[4] = {c.x, c.y, c.z, c.w};
        float bv[4] = {b.x, b.y, b.z, b.w};
        float wv[4] = {w0, w1, w2, w3};

        float d1[4], d2[4], bo[4];
#pragma unroll
        for (int i = 0; i < 4; i++) {
            // clause i on joined: sel = [-u1_i, -b_i, +u2_i], sgn = [-1,-1,+1]
            float s0 = -av[i];
            float s1 = -bv[i];
            float s2 =  cv[i];
            float m  = fmaxf(fmaxf(s0, s1), s2);
            float e0 = __expf(s0 - m);
            float e1 = __expf(s1 - m);
            float e2 = __expf(s2 - m);
            float inv = __fdividef(wv[i], e0 + e1 + e2);
            d1[i] = -e0 * inv;            // -> up[index1][i]
            bo[i] = bv[i] - e1 * inv;     // bp
            d2[i] =  e2 * inv;            // -> up[index2][i]
        }

        stcs_f4(reinterpret_cast<float4*>(bp) + e,
                make_float4(bo[0], bo[1], bo[2], bo[3]));   // streaming write

        red_add_v4(up + (size_t)i1 * 16, d1[0], d1[1], d1[2], d1[3]);
        red_add_v4(up + (size_t)i2 * 16, d2[0], d2[1], d2[2], d2[3]);
    }
}

extern "C" void kernel_launch(void* const* d_in, const int* in_sizes, int n_in,
                              void* d_out, int out_size) {
    const float* unary   = (const float*)d_in[0];
    const float* binary  = (const float*)d_in[1];
    const int*   index1  = (const int*)  d_in[2];
    const int*   index2  = (const int*)  d_in[3];
    const float* uw      = (const float*)d_in[4];
    const float* bw      = (const float*)d_in[5];

    int n_nodes = in_sizes[0] / 16;
    int n_edges = in_sizes[1] / 4;

    float* up = (float*)d_out;
    float* bp = up + (size_t)n_nodes * 16;

    unary_kernel<<<(n_nodes + 255) / 256, 256>>>(unary, uw, up, n_nodes);

    // One full-occupancy wave: 148 SMs x 8 blocks x 256 threads, grid-stride.
    int blocks = 148 * 8;
    int max_blocks = (n_edges + 255) / 256;
    if (blocks > max_blocks) blocks = max_blocks;
    edge_kernel<<<blocks, 256>>>(binary, index1, index2, bw, up, bp, n_edges);
}